// round 11
// baseline (speedup 1.0000x reference)
#include <cuda_runtime.h>
#include <math_constants.h>

// TropicalLinear forward: out[n,o] = max_j( x[n,j] + w[o,j] ) + bias[o]
//
// BARRIER-FREE main loop. 128 blocks x 512 threads, block tile 32n x 32o.
// Warp g (0..15) autonomously handles k in [64g, 64g+64): it loads its own
// x/w slices into a PRIVATE double-buffered smem region (stride 20 floats,
// conflict-free) and computes the whole 32x32 tile with a 4x8 register tile.
// Only __syncwarp between a warp's own STS and LDS -- no __syncthreads until
// the final 16->8->1 cross-warp max reduction.

#define N_DIM   128
#define IN_DIM  1024
#define OUT_DIM 1024
#define BMT     32
#define BOT     32
#define STR     20              // smem row stride floats (80B: 16B-aligned, 20r mod 32 distinct)
#define WXBUF   (BMT * STR)     // 640 floats: one 32x16 tile buffer
#define WTILE   (4 * WXBUF)     // 2560 floats per warp: {x,w} x {buf0,buf1}
#define SMEM_BYTES (16 * WTILE * 4)   // 163840 B
#define RSTR    36              // reduction row stride
#define RSZ     (BMT * RSTR)    // 1152 floats per partial region

extern __shared__ float sm[];

__global__ __launch_bounds__(512, 1)
void tropical_kernel(const float* __restrict__ x,
                     const float* __restrict__ w,
                     const float* __restrict__ bias,
                     float* __restrict__ out)
{
    const int t    = threadIdx.x;
    const int g    = t >> 5;         // warp id == k-group, 0..15
    const int lane = t & 31;
    const int tx   = lane & 3;       // o cols: tx + 4c, c=0..7
    const int ty   = lane >> 2;      // n rows: ty + 8r, r=0..3
    const int oBase = blockIdx.x * BOT;
    const int nBase = blockIdx.y * BMT;

    float* wb = sm + g * WTILE;      // this warp's private region
    // layout: [buf0 x | buf0 w | buf1 x | buf1 w], each WXBUF floats
#define XT(b) (wb + (b) * (2 * WXBUF))
#define WT(b) (wb + (b) * (2 * WXBUF) + WXBUF)

    // loader lane mapping: LDG j covers rows 8j..8j+7; lane -> (row l&7, 16B quarter l>>3)
    const int lr = lane & 7;
    const int lq = lane >> 3;
    const int kbase = g * 64;        // this warp's k range
    const float* xsrc = x + (nBase + lr) * IN_DIM + kbase + (lq << 2);
    const float* wsrc = w + (oBase + lr) * IN_DIM + kbase + (lq << 2);
    const int ssidx = lr * STR + (lq << 2);

    float acc[4][8];
#pragma unroll
    for (int r = 0; r < 4; r++)
#pragma unroll
        for (int c = 0; c < 8; c++)
            acc[r][c] = -CUDART_INF_F;

    float4 pfx[4], pfw[4];

    // ---- prologue: k-chunk 0 -> buffer 0 ----
#pragma unroll
    for (int j = 0; j < 4; j++) {
        pfx[j] = *(const float4*)(xsrc + j * 8 * IN_DIM);
        pfw[j] = *(const float4*)(wsrc + j * 8 * IN_DIM);
    }
#pragma unroll
    for (int j = 0; j < 4; j++) {
        *(float4*)&XT(0)[ssidx + j * 8 * STR] = pfx[j];
        *(float4*)&WT(0)[ssidx + j * 8 * STR] = pfw[j];
    }
    __syncwarp();

    // one 16B granule (4 k's): 12 LDS.128 + 256 math
#define GRANULE(b, K4)                                                      \
    {                                                                       \
        const float* px = XT(b) + ty * STR + (K4) * 4;                      \
        const float* pw = WT(b) + tx * STR + (K4) * 4;                      \
        const float4 a0 = *(const float4*)(px);                             \
        const float4 a1 = *(const float4*)(px + 8 * STR);                   \
        const float4 a2 = *(const float4*)(px + 16 * STR);                  \
        const float4 a3 = *(const float4*)(px + 24 * STR);                  \
        _Pragma("unroll")                                                   \
        for (int c = 0; c < 8; c++) {                                       \
            const float4 bv = *(const float4*)(pw + c * (4 * STR));         \
            acc[0][c] = fmaxf(acc[0][c], a0.x + bv.x);                      \
            acc[0][c] = fmaxf(acc[0][c], a0.y + bv.y);                      \
            acc[0][c] = fmaxf(acc[0][c], a0.z + bv.z);                      \
            acc[0][c] = fmaxf(acc[0][c], a0.w + bv.w);                      \
            acc[1][c] = fmaxf(acc[1][c], a1.x + bv.x);                      \
            acc[1][c] = fmaxf(acc[1][c], a1.y + bv.y);                      \
            acc[1][c] = fmaxf(acc[1][c], a1.z + bv.z);                      \
            acc[1][c] = fmaxf(acc[1][c], a1.w + bv.w);                      \
            acc[2][c] = fmaxf(acc[2][c], a2.x + bv.x);                      \
            acc[2][c] = fmaxf(acc[2][c], a2.y + bv.y);                      \
            acc[2][c] = fmaxf(acc[2][c], a2.z + bv.z);                      \
            acc[2][c] = fmaxf(acc[2][c], a2.w + bv.w);                      \
            acc[3][c] = fmaxf(acc[3][c], a3.x + bv.x);                      \
            acc[3][c] = fmaxf(acc[3][c], a3.y + bv.y);                      \
            acc[3][c] = fmaxf(acc[3][c], a3.z + bv.z);                      \
            acc[3][c] = fmaxf(acc[3][c], a3.w + bv.w);                      \
        }                                                                   \
    }

    // ---- 4 self-paced iterations (16 k's each), double-buffered ----
#pragma unroll 1
    for (int i = 0; i < 4; i++) {
        const int b = i & 1;

        if (i < 3) {   // prefetch next chunk
#pragma unroll
            for (int j = 0; j < 4; j++) {
                pfx[j] = *(const float4*)(xsrc + (i + 1) * 16 + j * 8 * IN_DIM);
                pfw[j] = *(const float4*)(wsrc + (i + 1) * 16 + j * 8 * IN_DIM);
            }
        }

        GRANULE(b, 0)
        GRANULE(b, 1)
        GRANULE(b, 2)
        GRANULE(b, 3)

        if (i < 3) {   // stage next chunk into the other buffer
            const int nb = b ^ 1;
#pragma unroll
            for (int j = 0; j < 4; j++) {
                *(float4*)&XT(nb)[ssidx + j * 8 * STR] = pfx[j];
                *(float4*)&WT(nb)[ssidx + j * 8 * STR] = pfw[j];
            }
            __syncwarp();
        }
    }

    // ---- cross-warp reduction: 16 -> 8 -> 1 (reuses the smem arena) ----
    __syncthreads();                       // all warps done with private tiles

    if (g >= 8) {                          // stage A: park partials
        float* red = sm + (g - 8) * RSZ;
#pragma unroll
        for (int r = 0; r < 4; r++)
#pragma unroll
            for (int c = 0; c < 8; c++)
                red[(ty + 8 * r) * RSTR + tx + 4 * c] = acc[r][c];
    }
    __syncthreads();

    if (g < 8) {                           // stage B: merge own accs
        float* red = sm + g * RSZ;
#pragma unroll
        for (int r = 0; r < 4; r++)
#pragma unroll
            for (int c = 0; c < 8; c++) {
                const int off = (ty + 8 * r) * RSTR + tx + 4 * c;
                red[off] = fmaxf(red[off], acc[r][c]);
            }
    }
    __syncthreads();

    // stage C: 8-way max + bias + store; 2 outputs per thread
#pragma unroll
    for (int j = 0; j < 2; j++) {
        const int idx = t + j * 512;       // 0..1023
        const int n = idx >> 5;
        const int o = idx & 31;
        const int ro = n * RSTR + o;
        float v0 = fmaxf(sm[ro],           sm[ro + RSZ]);
        float v1 = fmaxf(sm[ro + 2 * RSZ], sm[ro + 3 * RSZ]);
        float v2 = fmaxf(sm[ro + 4 * RSZ], sm[ro + 5 * RSZ]);
        float v3 = fmaxf(sm[ro + 6 * RSZ], sm[ro + 7 * RSZ]);
        float v  = fmaxf(fmaxf(v0, v1), fmaxf(v2, v3));
        out[(nBase + n) * OUT_DIM + oBase + o] = v + bias[oBase + o];
    }
}

extern "C" void kernel_launch(void* const* d_in, const int* in_sizes, int n_in,
                              void* d_out, int out_size)
{
    const float* x    = (const float*)d_in[0];   // [128, 1024]
    const float* w    = (const float*)d_in[1];   // [1024, 1024]
    const float* bias = (const float*)d_in[2];   // [1024]
    float* out = (float*)d_out;                  // [128, 1024]

    // 160KB dynamic smem (attribute set, not an allocation; deterministic)
    cudaFuncSetAttribute(tropical_kernel,
                         cudaFuncAttributeMaxDynamicSharedMemorySize, SMEM_BYTES);

    dim3 grid(OUT_DIM / BOT, N_DIM / BMT);       // 32 x 4 = 128 blocks
    tropical_kernel<<<grid, 512, SMEM_BYTES>>>(x, w, bias, out);
}

// round 12
// speedup vs baseline: 2.0713x; 2.0713x over previous
#include <cuda_runtime.h>
#include <math_constants.h>
#include <cstdint>

// TropicalLinear forward: out[n,o] = max_j( x[n,j] + w[o,j] ) + bias[o]
//
// R10 architecture + two fixes:
//  - BKT=256 -> only 4 main-loop barriers (seam-hole amortization)
//  - cp.async (LDGSTS) staging: gmem->smem with no register round-trip, no
//    prefetch registers (R11's spill cause), copy overlapped with compute.
// 128 blocks x 512 threads, block tile 32n x 32o. 16 k-group warps; warp g
// handles 16B-granules 4g..4g+3 of each 256-k slab (16 k's/iter, 64 total),
// computing the whole 32x32 tile with a 4x8 register tile.
// Row stride 260 floats (65 granules): bank phase = 4*tx, conflict-free.
// In-kernel 16->8->1 smem max-reduction.

#define N_DIM   128
#define IN_DIM  1024
#define OUT_DIM 1024
#define BMT     32
#define BOT     32
#define BKT     256             // k staged per iteration
#define NITER   (IN_DIM / BKT)  // 4
#define TSTR    260             // tile row stride floats (65 granules, odd)
#define TBUF    (BMT * TSTR)    // 8320 floats per tile buffer
#define SMEM_BYTES (4 * TBUF * 4)   // xs0,ws0,xs1,ws1 = 133120 B
#define RSTR    36              // reduction row stride
#define RSZ     (BMT * RSTR)    // 1152 floats per partial region

extern __shared__ float sm[];
#define XS(b) (sm + (b) * (2 * TBUF))
#define WS(b) (sm + (b) * (2 * TBUF) + TBUF)

__device__ __forceinline__ void cp16(uint32_t dst_smem, const float* src) {
    asm volatile("cp.async.cg.shared.global [%0], [%1], 16;"
                 :: "r"(dst_smem), "l"(src));
}

__global__ __launch_bounds__(512, 1)
void tropical_kernel(const float* __restrict__ x,
                     const float* __restrict__ w,
                     const float* __restrict__ bias,
                     float* __restrict__ out)
{
    const int t    = threadIdx.x;
    const int g    = t >> 5;         // k-group == warp id, 0..15
    const int lane = t & 31;
    const int tx   = lane & 3;       // o cols: tx + 4c, c=0..7
    const int ty   = lane >> 2;      // n rows: ty + 8r, r=0..3
    const int oBase = blockIdx.x * BOT;
    const int nBase = blockIdx.y * BMT;

    // loader mapping: thread t stages granules (t&15)+16j, j=0..3, of row t>>4
    const int lrow = t >> 4;         // 0..31
    const int lgr  = t & 15;
    const float* xg = x + (nBase + lrow) * IN_DIM + (lgr << 2);
    const float* wg = w + (oBase + lrow) * IN_DIM + (lgr << 2);
    const uint32_t smbase = (uint32_t)__cvta_generic_to_shared(sm);
    const uint32_t sx = smbase + (lrow * TSTR + (lgr << 2)) * 4;   // into XS(0)
    const uint32_t swb = sx + TBUF * 4;                            // into WS(0)
    const int BUFB = 2 * TBUF * 4;   // byte stride between buffers

    const int goff = g << 4;         // float offset of granule 4g in a row

    float acc[4][8];
#pragma unroll
    for (int r = 0; r < 4; r++)
#pragma unroll
        for (int c = 0; c < 8; c++)
            acc[r][c] = -CUDART_INF_F;

    // ---- prologue: stage slab 0 into buffer 0 ----
#pragma unroll
    for (int j = 0; j < 4; j++) {
        cp16(sx  + j * 64 * 4, xg + j * 64);
        cp16(swb + j * 64 * 4, wg + j * 64);
    }
    asm volatile("cp.async.commit_group;");
    asm volatile("cp.async.wait_group 0;");
    __syncthreads();

    // one 16B granule (4 k's): 12 LDS.128 + 256 math
#define GRANULE(b, G)                                                       \
    {                                                                       \
        const float* px = XS(b) + ty * TSTR + (G);                          \
        const float* pw = WS(b) + tx * TSTR + (G);                          \
        const float4 a0 = *(const float4*)(px);                             \
        const float4 a1 = *(const float4*)(px + 8 * TSTR);                  \
        const float4 a2 = *(const float4*)(px + 16 * TSTR);                 \
        const float4 a3 = *(const float4*)(px + 24 * TSTR);                 \
        _Pragma("unroll")                                                   \
        for (int c = 0; c < 8; c++) {                                       \
            const float4 bv = *(const float4*)(pw + c * (4 * TSTR));        \
            acc[0][c] = fmaxf(acc[0][c], a0.x + bv.x);                      \
            acc[0][c] = fmaxf(acc[0][c], a0.y + bv.y);                      \
            acc[0][c] = fmaxf(acc[0][c], a0.z + bv.z);                      \
            acc[0][c] = fmaxf(acc[0][c], a0.w + bv.w);                      \
            acc[1][c] = fmaxf(acc[1][c], a1.x + bv.x);                      \
            acc[1][c] = fmaxf(acc[1][c], a1.y + bv.y);                      \
            acc[1][c] = fmaxf(acc[1][c], a1.z + bv.z);                      \
            acc[1][c] = fmaxf(acc[1][c], a1.w + bv.w);                      \
            acc[2][c] = fmaxf(acc[2][c], a2.x + bv.x);                      \
            acc[2][c] = fmaxf(acc[2][c], a2.y + bv.y);                      \
            acc[2][c] = fmaxf(acc[2][c], a2.z + bv.z);                      \
            acc[2][c] = fmaxf(acc[2][c], a2.w + bv.w);                      \
            acc[3][c] = fmaxf(acc[3][c], a3.x + bv.x);                      \
            acc[3][c] = fmaxf(acc[3][c], a3.y + bv.y);                      \
            acc[3][c] = fmaxf(acc[3][c], a3.z + bv.z);                      \
            acc[3][c] = fmaxf(acc[3][c], a3.w + bv.w);                      \
        }                                                                   \
    }

#pragma unroll 1
    for (int i = 0; i < NITER; i++) {
        const int b = i & 1;

        if (i < NITER - 1) {
            // stage next slab into the other buffer (async, runs under compute)
            const int nb = b ^ 1;
            const float* xp = xg + (i + 1) * BKT;
            const float* wp = wg + (i + 1) * BKT;
#pragma unroll
            for (int j = 0; j < 4; j++) {
                cp16(sx  + nb * BUFB + j * 64 * 4, xp + j * 64);
                cp16(swb + nb * BUFB + j * 64 * 4, wp + j * 64);
            }
            asm volatile("cp.async.commit_group;");
        }

        GRANULE(b, goff)
        GRANULE(b, goff + 4)
        GRANULE(b, goff + 8)
        GRANULE(b, goff + 12)

        if (i < NITER - 1) {
            asm volatile("cp.async.wait_group 0;");
            __syncthreads();
        }
    }

    // ---- cross-warp reduction: 16 -> 8 -> 1 (reuses the smem arena) ----
    __syncthreads();                       // all tile reads done before overwrite

    if (g >= 8) {                          // stage A: park partials
        float* red = sm + (g - 8) * RSZ;
#pragma unroll
        for (int r = 0; r < 4; r++)
#pragma unroll
            for (int c = 0; c < 8; c++)
                red[(ty + 8 * r) * RSTR + tx + 4 * c] = acc[r][c];
    }
    __syncthreads();

    if (g < 8) {                           // stage B: merge own accs
        float* red = sm + g * RSZ;
#pragma unroll
        for (int r = 0; r < 4; r++)
#pragma unroll
            for (int c = 0; c < 8; c++) {
                const int off = (ty + 8 * r) * RSTR + tx + 4 * c;
                red[off] = fmaxf(red[off], acc[r][c]);
            }
    }
    __syncthreads();

    // stage C: 8-way max + bias + store; 2 outputs per thread
#pragma unroll
    for (int j = 0; j < 2; j++) {
        const int idx = t + j * 512;       // 0..1023
        const int n = idx >> 5;
        const int o = idx & 31;
        const int ro = n * RSTR + o;
        float v0 = fmaxf(sm[ro],           sm[ro + RSZ]);
        float v1 = fmaxf(sm[ro + 2 * RSZ], sm[ro + 3 * RSZ]);
        float v2 = fmaxf(sm[ro + 4 * RSZ], sm[ro + 5 * RSZ]);
        float v3 = fmaxf(sm[ro + 6 * RSZ], sm[ro + 7 * RSZ]);
        float v  = fmaxf(fmaxf(v0, v1), fmaxf(v2, v3));
        out[(nBase + n) * OUT_DIM + oBase + o] = v + bias[oBase + o];
    }
}

extern "C" void kernel_launch(void* const* d_in, const int* in_sizes, int n_in,
                              void* d_out, int out_size)
{
    const float* x    = (const float*)d_in[0];   // [128, 1024]
    const float* w    = (const float*)d_in[1];   // [1024, 1024]
    const float* bias = (const float*)d_in[2];   // [1024]
    float* out = (float*)d_out;                  // [128, 1024]

    // 130KB dynamic smem (attribute set, not an allocation; deterministic)
    cudaFuncSetAttribute(tropical_kernel,
                         cudaFuncAttributeMaxDynamicSharedMemorySize, SMEM_BYTES);

    dim3 grid(OUT_DIM / BOT, N_DIM / BMT);       // 32 x 4 = 128 blocks
    tropical_kernel<<<grid, 512, SMEM_BYTES>>>(x, w, bias, out);
}

// round 14
// speedup vs baseline: 2.0949x; 1.0114x over previous
#include <cuda_runtime.h>
#include <math_constants.h>
#include <cstdint>

// TropicalLinear forward: out[n,o] = max_j( x[n,j] + w[o,j] ) + bias[o]
//
// DESYNCHRONIZED BARRIER DOMAINS (R13 resubmit; prior run died to infra).
// 128 blocks x 512 threads, tile 32n x 32o.
// 4 groups x 4 warps (warps 4q..4q+3 -> one warp per SMSP per group).
// Group q owns k in [256q, 256q+256): 4 iterations x 64-k slabs, private
// double-buffered smem staged with cp.async (no prefetch registers), synced
// ONLY by named barrier (q+1, 128 threads). Warp r of a group computes the
// whole 32x32 tile over granules {r, r+4, r+8, r+12} of each slab (4x8 reg
// tile, 12 LDS + 256 math per granule). Each SMSP hosts 4 warps from 4
// different barrier domains -> a seam never stalls a whole SMSP.
// In-kernel 16->8->1 smem max-reduction (block barriers only at the end).

#define N_DIM   128
#define IN_DIM  1024
#define OUT_DIM 1024
#define BMT     32
#define BOT     32
#define STR     68               // smem row stride floats (17 granules, odd)
#define TILEF   (BMT * STR)      // 2176 floats: one 32x64 tile
#define GRPF    (4 * TILEF)      // per-group: {x,w} x {buf0,buf1} = 8704 floats
#define SMEM_BYTES (4 * GRPF * 4)    // 139264 B
#define RSTR    36               // reduction row stride
#define RSZ     (BMT * RSTR)     // 1152 floats per partial region

extern __shared__ float sm[];

__device__ __forceinline__ void cp16(uint32_t dst_smem, const float* src) {
    asm volatile("cp.async.cg.shared.global [%0], [%1], 16;"
                 :: "r"(dst_smem), "l"(src));
}
__device__ __forceinline__ void cp_commit() {
    asm volatile("cp.async.commit_group;");
}
__device__ __forceinline__ void cp_wait0() {
    asm volatile("cp.async.wait_group 0;");
}
__device__ __forceinline__ void group_bar(int id) {
    asm volatile("bar.sync %0, 128;" :: "r"(id) : "memory");
}

__global__ __launch_bounds__(512, 1)
void tropical_kernel(const float* __restrict__ x,
                     const float* __restrict__ w,
                     const float* __restrict__ bias,
                     float* __restrict__ out)
{
    const int t    = threadIdx.x;
    const int g    = t >> 5;          // warp id 0..15
    const int q    = t >> 7;          // barrier group 0..3 (warps 4q..4q+3)
    const int r    = (t >> 5) & 3;    // warp-in-group 0..3
    const int lane = t & 31;
    const int tx   = lane & 3;        // o cols: tx + 4c, c=0..7
    const int ty   = lane >> 2;       // n rows: ty + 8r', r'=0..3
    const int oBase = blockIdx.x * BOT;
    const int nBase = blockIdx.y * BMT;

    float* grp = sm + q * GRPF;       // group-private region
#define XT(b) (grp + (b) * (2 * TILEF))
#define WT(b) (grp + (b) * (2 * TILEF) + TILEF)

    // loaders (128 threads/group): u = t&127 -> (granule, base row)
    const int u    = t & 127;
    const int lgr  = u & 15;          // granule 0..15
    const int lr0  = u >> 4;          // base row 0..7 (covers +8,+16,+24 via j)
    const int kbase = q * 256;        // group k origin
    const float* xsrc = x + (nBase + lr0) * IN_DIM + kbase + (lgr << 2);
    const float* wsrc = w + (oBase + lr0) * IN_DIM + kbase + (lgr << 2);
    const uint32_t grpb = (uint32_t)__cvta_generic_to_shared(grp);
    const uint32_t sxd  = grpb + (lr0 * STR + (lgr << 2)) * 4;   // into XT(0)
    const uint32_t swd  = sxd + TILEF * 4;                       // into WT(0)
    const int BUFB = 2 * TILEF * 4;   // byte stride buf0 -> buf1

    float acc[4][8];
#pragma unroll
    for (int rr = 0; rr < 4; rr++)
#pragma unroll
        for (int c = 0; c < 8; c++)
            acc[rr][c] = -CUDART_INF_F;

    // stage slab `s` (64 k's at kbase + 64s) into buffer b
#define STAGE(b, s)                                                         \
    {                                                                       \
        const float* xp = xsrc + (s) * 64;                                  \
        const float* wp = wsrc + (s) * 64;                                  \
        _Pragma("unroll")                                                   \
        for (int j = 0; j < 4; j++) {                                       \
            cp16(sxd + (b) * BUFB + j * (8 * STR * 4), xp + j * 8 * IN_DIM);\
            cp16(swd + (b) * BUFB + j * (8 * STR * 4), wp + j * 8 * IN_DIM);\
        }                                                                   \
        cp_commit();                                                        \
    }

    // one 16B granule (4 k's): 12 LDS.128 + 256 math
#define GRANULE(b, G)                                                       \
    {                                                                       \
        const float* px = XT(b) + ty * STR + (G) * 4;                       \
        const float* pw = WT(b) + tx * STR + (G) * 4;                       \
        const float4 a0 = *(const float4*)(px);                             \
        const float4 a1 = *(const float4*)(px + 8 * STR);                   \
        const float4 a2 = *(const float4*)(px + 16 * STR);                  \
        const float4 a3 = *(const float4*)(px + 24 * STR);                  \
        _Pragma("unroll")                                                   \
        for (int c = 0; c < 8; c++) {                                       \
            const float4 bv = *(const float4*)(pw + c * (4 * STR));         \
            acc[0][c] = fmaxf(acc[0][c], a0.x + bv.x);                      \
            acc[0][c] = fmaxf(acc[0][c], a0.y + bv.y);                      \
            acc[0][c] = fmaxf(acc[0][c], a0.z + bv.z);                      \
            acc[0][c] = fmaxf(acc[0][c], a0.w + bv.w);                      \
            acc[1][c] = fmaxf(acc[1][c], a1.x + bv.x);                      \
            acc[1][c] = fmaxf(acc[1][c], a1.y + bv.y);                      \
            acc[1][c] = fmaxf(acc[1][c], a1.z + bv.z);                      \
            acc[1][c] = fmaxf(acc[1][c], a1.w + bv.w);                      \
            acc[2][c] = fmaxf(acc[2][c], a2.x + bv.x);                      \
            acc[2][c] = fmaxf(acc[2][c], a2.y + bv.y);                      \
            acc[2][c] = fmaxf(acc[2][c], a2.z + bv.z);                      \
            acc[2][c] = fmaxf(acc[2][c], a2.w + bv.w);                      \
            acc[3][c] = fmaxf(acc[3][c], a3.x + bv.x);                      \
            acc[3][c] = fmaxf(acc[3][c], a3.y + bv.y);                      \
            acc[3][c] = fmaxf(acc[3][c], a3.z + bv.z);                      \
            acc[3][c] = fmaxf(acc[3][c], a3.w + bv.w);                      \
        }                                                                   \
    }

    // ---- prologue: slab 0 -> buffer 0 ----
    STAGE(0, 0)
    cp_wait0();
    group_bar(q + 1);

    // ---- 4 self-paced group iterations ----
#pragma unroll 1
    for (int i = 0; i < 4; i++) {
        const int b = i & 1;

        if (i < 3) STAGE(b ^ 1, i + 1)     // async copy runs under compute

        GRANULE(b, r)
        GRANULE(b, r + 4)
        GRANULE(b, r + 8)
        GRANULE(b, r + 12)

        if (i < 3) {
            cp_wait0();                    // own copies landed
            group_bar(q + 1);              // group-wide visibility
        }
    }

    // ---- cross-warp reduction: 16 -> 8 -> 1 (reuses the smem arena) ----
    __syncthreads();                       // ALL groups done with tiles

    if (g >= 8) {                          // stage A: park partials
        float* red = sm + (g - 8) * RSZ;
#pragma unroll
        for (int rr = 0; rr < 4; rr++)
#pragma unroll
            for (int c = 0; c < 8; c++)
                red[(ty + 8 * rr) * RSTR + tx + 4 * c] = acc[rr][c];
    }
    __syncthreads();

    if (g < 8) {                           // stage B: merge own accs
        float* red = sm + g * RSZ;
#pragma unroll
        for (int rr = 0; rr < 4; rr++)
#pragma unroll
            for (int c = 0; c < 8; c++) {
                const int off = (ty + 8 * rr) * RSTR + tx + 4 * c;
                red[off] = fmaxf(red[off], acc[rr][c]);
            }
    }
    __syncthreads();

    // stage C: 8-way max + bias + store; 2 outputs per thread
#pragma unroll
    for (int j = 0; j < 2; j++) {
        const int idx = t + j * 512;       // 0..1023
        const int n = idx >> 5;
        const int o = idx & 31;
        const int ro = n * RSTR + o;
        float v0 = fmaxf(sm[ro],           sm[ro + RSZ]);
        float v1 = fmaxf(sm[ro + 2 * RSZ], sm[ro + 3 * RSZ]);
        float v2 = fmaxf(sm[ro + 4 * RSZ], sm[ro + 5 * RSZ]);
        float v3 = fmaxf(sm[ro + 6 * RSZ], sm[ro + 7 * RSZ]);
        float v  = fmaxf(fmaxf(v0, v1), fmaxf(v2, v3));
        out[(nBase + n) * OUT_DIM + oBase + o] = v + bias[oBase + o];
    }
}

extern "C" void kernel_launch(void* const* d_in, const int* in_sizes, int n_in,
                              void* d_out, int out_size)
{
    const float* x    = (const float*)d_in[0];   // [128, 1024]
    const float* w    = (const float*)d_in[1];   // [1024, 1024]
    const float* bias = (const float*)d_in[2];   // [1024]
    float* out = (float*)d_out;                  // [128, 1024]

    // 136KB dynamic smem (attribute set, not an allocation; deterministic)
    cudaFuncSetAttribute(tropical_kernel,
                         cudaFuncAttributeMaxDynamicSharedMemorySize, SMEM_BYTES);

    dim3 grid(OUT_DIM / BOT, N_DIM / BMT);       // 32 x 4 = 128 blocks
    tropical_kernel<<<grid, 512, SMEM_BYTES>>>(x, w, bias, out);
}